// round 10
// baseline (speedup 1.0000x reference)
#include <cuda_runtime.h>
#include <math.h>

#define BB   64
#define CI   16
#define LEN  8192
#define N0   64
#define F0   33
#define T0   128
#define N1   256
#define F1   129
#define T1   32
#define CO   32

// -------- scratch (device globals; no runtime allocation) --------
__device__ float2 g_p0[BB * T0 * F0 * CI];   // (b,t,f,c) complex
__device__ float2 g_p1[BB * T1 * F1 * CI];   // (b,t,f1,c) complex (becomes acc1)
__device__ float2 g_out1[BB * T1 * F1 * CO]; // head1 spectrum
__device__ float4 g_stats[2 * BB];           // per (head,b): scale, shift_re, shift_im
__device__ float  g_partf[384];              // [0:128)=sr, [128:256)=si, [256:384)=sq; slot=head*64+b

__global__ void k_zero() {
    int i = threadIdx.x;
    if (i < 384) g_partf[i] = 0.f;
}

// ================= STFT n=64 : 128 thr, fold symmetry + 2f x 2c tiling + fused stats =================
__global__ void k_stft0(const float* __restrict__ x) {
    int b = blockIdx.x >> 7;
    int t = blockIdx.x & 127;
    __shared__ float  sx[CI * 65];
    __shared__ float2 suv[CI * 33];      // (u,v); slot 0 = (x0, x32)
    __shared__ float2 tw[N0];
    int tid = threadIdx.x;
    if (tid < N0) {
        float s, c; sincospif(tid * (1.0f / 32.0f), &s, &c);
        tw[tid] = make_float2(c, s);
    }
    for (int i = tid; i < CI * N0; i += 128) {
        int c = i >> 6, s = i & 63;
        int src = t * N0 + s - 32;
        if (src < 0) src = -src;
        if (src >= LEN) src = 2 * LEN - 2 - src;
        sx[c * 65 + s] = x[(b * CI + c) * LEN + src];
    }
    __syncthreads();
    for (int i = tid; i < CI * 32; i += 128) {
        int c = i >> 5, s = i & 31;
        if (s == 0) {
            suv[c * 33] = make_float2(sx[c * 65], sx[c * 65 + 32]);
        } else {
            float a = sx[c * 65 + s];
            float d = sx[c * 65 + 64 - s];
            suv[c * 33 + s] = make_float2(a + d, a - d);
        }
    }
    __syncthreads();
    int frame = (b * T0 + t) * (F0 * CI);
    int u  = tid >> 3;        // f in {u, u+16}
    int cg = tid & 7;         // c in {cg, cg+8}
    float r00 = 0.f, i00 = 0.f, r01 = 0.f, i01 = 0.f;
    float r10 = 0.f, i10 = 0.f, r11 = 0.f, i11 = 0.f;
    int ia = 0, ib = 0;
    #pragma unroll 4
    for (int s = 1; s < 32; s++) {
        ia = (ia + u) & 63;
        ib = (ib + u + 16) & 63;
        float2 a0 = suv[cg * 33 + s];
        float2 a1 = suv[(cg + 8) * 33 + s];
        float2 w0 = tw[ia];
        float2 w1 = tw[ib];
        r00 += a0.x * w0.x; i00 -= a0.y * w0.y;
        r01 += a1.x * w0.x; i01 -= a1.y * w0.y;
        r10 += a0.x * w1.x; i10 -= a0.y * w1.y;
        r11 += a1.x * w1.x; i11 -= a1.y * w1.y;
    }
    float2 e0 = suv[cg * 33];
    float2 e1 = suv[(cg + 8) * 33];
    float sg = (u & 1) ? -1.f : 1.f;
    float ea = e0.x + sg * e0.y, eb = e1.x + sg * e1.y;
    float v00 = r00 + ea, v01 = r01 + eb, v10 = r10 + ea, v11 = r11 + eb;
    g_p0[frame + u * CI + cg]            = make_float2(v00, i00);
    g_p0[frame + u * CI + cg + 8]        = make_float2(v01, i01);
    g_p0[frame + (u + 16) * CI + cg]     = make_float2(v10, i10);
    g_p0[frame + (u + 16) * CI + cg + 8] = make_float2(v11, i11);
    float sr = v00 + v01 + v10 + v11;
    float si = i00 + i01 + i10 + i11;
    float sq = v00 * v00 + i00 * i00 + v01 * v01 + i01 * i01
             + v10 * v10 + i10 * i10 + v11 * v11 + i11 * i11;
    if (tid < 16) {
        const float2* uv = suv + tid * 33;
        float re = 0.f;
        #pragma unroll 4
        for (int s = 1; s < 32; s++) {
            float uu = uv[s].x;
            re += (s & 1) ? -uu : uu;
        }
        float2 e = uv[0];
        float val = re + e.x + e.y;
        g_p0[frame + 32 * CI + tid] = make_float2(val, 0.f);
        sr += val; sq += val * val;
    }
    // block reduce (4 warps) + atomic
    #pragma unroll
    for (int off = 16; off; off >>= 1) {
        sr += __shfl_xor_sync(0xffffffffu, sr, off);
        si += __shfl_xor_sync(0xffffffffu, si, off);
        sq += __shfl_xor_sync(0xffffffffu, sq, off);
    }
    __shared__ float wr[4], wi[4], wq[4];
    if ((tid & 31) == 0) { wr[tid >> 5] = sr; wi[tid >> 5] = si; wq[tid >> 5] = sq; }
    __syncthreads();
    if (tid == 0) {
        float a = wr[0] + wr[1] + wr[2] + wr[3];
        float bb2 = wi[0] + wi[1] + wi[2] + wi[3];
        float c = wq[0] + wq[1] + wq[2] + wq[3];
        atomicAdd(&g_partf[b], a);
        atomicAdd(&g_partf[128 + b], bb2);
        atomicAdd(&g_partf[256 + b], c);
    }
}

// ===== STFT n=256 : fold + parity split + float4 loads; skip rows f%4==0 (merge rewrites); fused stats =====
__global__ void k_stft1(const float* __restrict__ x) {
    int b = blockIdx.x >> 5;
    int t = blockIdx.x & 31;
    __shared__ float  sx[CI * N1];
    __shared__ float2 suv[CI * 130];     // (u,v); pitch 130 (float4-aligned); slot 0 = (x0, x128)
    __shared__ float2 tw[N1];
    int tid = threadIdx.x;
    for (int i = tid; i < N1; i += 128) {
        float s, c; sincospif(i * (1.0f / 128.0f), &s, &c);
        tw[i] = make_float2(c, s);
    }
    for (int i = tid; i < CI * N1; i += 128) {
        int c = i >> 8, s = i & 255;
        int src = t * N1 + s - 128;
        if (src < 0) src = -src;
        if (src >= LEN) src = 2 * LEN - 2 - src;
        sx[i] = x[(b * CI + c) * LEN + src];
    }
    __syncthreads();
    for (int i = tid; i < CI * 128; i += 128) {
        int c = i >> 7, s = i & 127;
        if (s == 0) {
            suv[c * 130] = make_float2(sx[c << 8], sx[(c << 8) + 128]);
        } else {
            float a = sx[(c << 8) + s];
            float d = sx[(c << 8) + 256 - s];
            suv[c * 130 + s] = make_float2(a + d, a - d);
        }
    }
    __syncthreads();
    int frame = (b * T1 + t) * (F1 * CI);
    int u  = tid >> 3;        // f = u + 16k, k=0..3 (f in 0..63; mirrors 65..128)
    int cg = tid & 7;         // c in {cg, cg+8}
    float Ce[4][2], Co[4][2], Se[4][2], So[4][2];
    int io[4], ie[4], fq[4];
    #pragma unroll
    for (int k = 0; k < 4; k++) {
        fq[k] = u + 16 * k;
        io[k] = fq[k];
        ie[k] = 0;
        #pragma unroll
        for (int m = 0; m < 2; m++) { Ce[k][m] = Co[k][m] = Se[k][m] = So[k][m] = 0.f; }
    }
    const float4* uvA4 = (const float4*)(suv + cg * 130);
    const float4* uvB4 = (const float4*)(suv + (cg + 8) * 130);
    // h = 0 : .xy = (x0, x128) [handled at end], .zw = (u1,v1) for odd s=1
    float4 h0A = uvA4[0], h0B = uvB4[0];
    #pragma unroll
    for (int k = 0; k < 4; k++) {
        float2 w = tw[io[k]];
        Co[k][0] += h0A.z * w.x;  So[k][0] += h0A.w * w.y;
        Co[k][1] += h0B.z * w.x;  So[k][1] += h0B.w * w.y;
    }
    #pragma unroll 2
    for (int h = 1; h < 64; h++) {
        float4 A = uvA4[h];       // (u[2h], v[2h], u[2h+1], v[2h+1])
        float4 Bv = uvB4[h];
        #pragma unroll
        for (int k = 0; k < 4; k++) {
            ie[k] = (ie[k] + 2 * fq[k]) & 255;
            io[k] = (io[k] + 2 * fq[k]) & 255;
            float2 we = tw[ie[k]];
            float2 wo = tw[io[k]];
            Ce[k][0] += A.x * we.x;   Se[k][0] += A.y * we.y;
            Co[k][0] += A.z * wo.x;   So[k][0] += A.w * wo.y;
            Ce[k][1] += Bv.x * we.x;  Se[k][1] += Bv.y * we.y;
            Co[k][1] += Bv.z * wo.x;  So[k][1] += Bv.w * wo.y;
        }
    }
    float sr = 0.f, si = 0.f, sq = 0.f;
    if (u & 3) {      // rows f%4==0 are overwritten by merge: skip writes + stats
        float ea = h0A.x + ((u & 1) ? -h0A.y : h0A.y);
        float eb = h0B.x + ((u & 1) ? -h0B.y : h0B.y);
        #pragma unroll
        for (int k = 0; k < 4; k++) {
            int f = fq[k];
            float r0 = ea + Ce[k][0] + Co[k][0], m0 = -(Se[k][0] + So[k][0]);
            float r1 = ea + Ce[k][0] - Co[k][0], m1 =   Se[k][0] - So[k][0];
            float r2 = eb + Ce[k][1] + Co[k][1], m2 = -(Se[k][1] + So[k][1]);
            float r3 = eb + Ce[k][1] - Co[k][1], m3 =   Se[k][1] - So[k][1];
            g_p1[frame + f * CI + cg]             = make_float2(r0, m0);
            g_p1[frame + (128 - f) * CI + cg]     = make_float2(r1, m1);
            g_p1[frame + f * CI + cg + 8]         = make_float2(r2, m2);
            g_p1[frame + (128 - f) * CI + cg + 8] = make_float2(r3, m3);
            sr += r0 + r1 + r2 + r3;
            si += m0 + m1 + m2 + m3;
            sq += r0 * r0 + m0 * m0 + r1 * r1 + m1 * m1
                + r2 * r2 + m2 * m2 + r3 * r3 + m3 * m3;
        }
    }
    #pragma unroll
    for (int off = 16; off; off >>= 1) {
        sr += __shfl_xor_sync(0xffffffffu, sr, off);
        si += __shfl_xor_sync(0xffffffffu, si, off);
        sq += __shfl_xor_sync(0xffffffffu, sq, off);
    }
    __shared__ float wr[4], wi[4], wq[4];
    if ((tid & 31) == 0) { wr[tid >> 5] = sr; wi[tid >> 5] = si; wq[tid >> 5] = sq; }
    __syncthreads();
    if (tid == 0) {
        float a = wr[0] + wr[1] + wr[2] + wr[3];
        float bb2 = wi[0] + wi[1] + wi[2] + wi[3];
        float c = wq[0] + wq[1] + wq[2] + wq[3];
        atomicAdd(&g_partf[64 + b], a);
        atomicAdd(&g_partf[128 + 64 + b], bb2);
        atomicAdd(&g_partf[256 + 64 + b], c);
    }
}

// ================= attention merge (b-aligned grid) + fused stats =================
__global__ void k_merge(const float* __restrict__ mk_r, const float* __restrict__ mk_i,
                        const float* __restrict__ mb_r, const float* __restrict__ mb_i) {
    __shared__ float skr[16], ski[16], sbr[4], sbi[4];
    int tid = threadIdx.x;
    int b = blockIdx.y;
    if (tid < 16) { skr[tid] = mk_r[tid]; ski[tid] = mk_i[tid]; }
    if (tid < 4)  { sbr[tid] = mb_r[tid]; sbi[tid] = mb_i[tid]; }
    __syncthreads();
    int item = blockIdx.x * 256 + tid;
    float sr = 0.f, si2 = 0.f, sq = 0.f;
    if (item < T1 * F0 * CI) {
        int c    = item & 15;
        int rest = item >> 4;
        int f    = rest % F0;
        int t    = rest / F0;
        int base = ((b * T0 + 4 * t) * F0 + f) * CI + c;
        float2 pm[4];
        #pragma unroll
        for (int r = 0; r < 4; r++) pm[r] = g_p0[base + r * (F0 * CI)];
        float av[4];
        #pragma unroll
        for (int s = 0; s < 4; s++) {
            float ar = sbr[s], ai = sbi[s];
            #pragma unroll
            for (int r = 0; r < 4; r++) {
                float kr = skr[r * 4 + s], ki = ski[r * 4 + s];
                ar += pm[r].x * kr - pm[r].y * ki;
                ai += pm[r].x * ki + pm[r].y * kr;
            }
            av[s] = sqrtf(ar * ar + ai * ai);
        }
        float m = fmaxf(fmaxf(av[0], av[1]), fmaxf(av[2], av[3]));
        float e0 = expf(av[0] - m), e1 = expf(av[1] - m), e2 = expf(av[2] - m), e3 = expf(av[3] - m);
        float inv = 4.0f / (e0 + e1 + e2 + e3);
        float re = (pm[0].x * e0 + pm[1].x * e1 + pm[2].x * e2 + pm[3].x * e3) * inv;
        float im = (pm[0].y * e0 + pm[1].y * e1 + pm[2].y * e2 + pm[3].y * e3) * inv;
        g_p1[((b * T1 + t) * F1 + 4 * f) * CI + c] = make_float2(re, im);
        sr = re; si2 = im; sq = re * re + im * im;
    }
    #pragma unroll
    for (int off = 16; off; off >>= 1) {
        sr  += __shfl_xor_sync(0xffffffffu, sr, off);
        si2 += __shfl_xor_sync(0xffffffffu, si2, off);
        sq  += __shfl_xor_sync(0xffffffffu, sq, off);
    }
    __shared__ float wr[8], wi[8], wq[8];
    if ((tid & 31) == 0) { wr[tid >> 5] = sr; wi[tid >> 5] = si2; wq[tid >> 5] = sq; }
    __syncthreads();
    if (tid == 0) {
        float a = 0.f, bb2 = 0.f, c = 0.f;
        #pragma unroll
        for (int w = 0; w < 8; w++) { a += wr[w]; bb2 += wi[w]; c += wq[w]; }
        atomicAdd(&g_partf[64 + b], a);
        atomicAdd(&g_partf[128 + 64 + b], bb2);
        atomicAdd(&g_partf[256 + 64 + b], c);
    }
}

__global__ void k_stats_fin(const float* __restrict__ gam, const float* __restrict__ bet) {
    int i = threadIdx.x;
    if (i >= 128) return;
    double sr = (double)g_partf[i];
    double si = (double)g_partf[128 + i];
    double sq = (double)g_partf[256 + i];
    int head = i >> 6, b = i & 63;
    int N = head ? (T1 * F1 * CI) : (T0 * F0 * CI);
    double mur = sr / N, mui = si / N;
    double var = sq / N - mur * mur - mui * mui;
    double istd = rsqrt(var + 1e-5);
    float g = gam[head * BB + b], be = bet[head * BB + b];
    float s = (float)(g * istd);
    g_stats[i] = make_float4(s, be - (float)mur * s, -(float)mui * s, 0.f);
}

// ================= head0 fused: BN + einsum (o-pair, float4 x) + iSTFT-64 + bias/relu =================
__global__ void k_head0(const float* __restrict__ fk0_r, const float* __restrict__ fk0_i,
                        const float* __restrict__ pbias, float* __restrict__ y) {
    extern __shared__ char smraw[];
    float2* fk  = (float2*)smraw;           // F0*CI*CO
    float2* sx  = fk + F0 * CI * CO;
    float2* so  = sx + F0 * CI;
    float2* tw  = so + F0 * CO;
    float*  sfr = (float*)(tw + 64);

    int tid = threadIdx.x;
    int b   = blockIdx.x >> 3;
    int grp = blockIdx.x & 7;

    for (int i = tid; i < F0 * CI * CO; i += 256)
        fk[i] = make_float2(fk0_r[i], fk0_i[i]);
    if (tid < 64) {
        float s, c; sincospif(tid * (1.0f / 32.0f), &s, &c);
        tw[tid] = make_float2(c, s);
    }
    float4 st = g_stats[b];
    const float inv = 1.0f / 64.0f;

    for (int k = 0; k < 16; k++) {
        int t = grp * 16 + k;
        __syncthreads();
        int fb = (b * T0 + t) * (F0 * CI);
        for (int i = tid; i < F0 * CI; i += 256) {
            float2 z = g_p0[fb + i];
            sx[i] = make_float2(z.x * st.x + st.y, z.y * st.x + st.z);
        }
        __syncthreads();
        // einsum: items = f*16 + og; thread handles o = og, og+16
        for (int it = tid; it < F0 * 16; it += 256) {
            int og = it & 15, f = it >> 4;
            const float4* xr = (const float4*)(sx + f * CI);
            const float2* kk = fk + f * CI * CO;
            float re0 = 0.f, im0 = 0.f, re1 = 0.f, im1 = 0.f;
            #pragma unroll
            for (int c2 = 0; c2 < 8; c2++) {
                float4 xv = xr[c2];
                float2 ka0 = kk[(2 * c2) * CO + og];
                float2 kb0 = kk[(2 * c2) * CO + og + 16];
                float2 ka1 = kk[(2 * c2 + 1) * CO + og];
                float2 kb1 = kk[(2 * c2 + 1) * CO + og + 16];
                re0 += xv.x * ka0.x - xv.y * ka0.y;  im0 += xv.x * ka0.y + xv.y * ka0.x;
                re0 += xv.z * ka1.x - xv.w * ka1.y;  im0 += xv.z * ka1.y + xv.w * ka1.x;
                re1 += xv.x * kb0.x - xv.y * kb0.y;  im1 += xv.x * kb0.y + xv.y * kb0.x;
                re1 += xv.z * kb1.x - xv.w * kb1.y;  im1 += xv.z * kb1.y + xv.w * kb1.x;
            }
            so[f * CO + og]      = make_float2(re0, im0);
            so[f * CO + og + 16] = make_float2(re1, im1);
        }
        __syncthreads();
        // iSTFT-64, 2j x 2o register tile
        {
            int u  = tid >> 4;       // jp in {u, u+16}
            int o0 = tid & 15;       // o in {o0, o0+16}
            float c00 = 0.f, s00 = 0.f, c01 = 0.f, s01 = 0.f;
            float c10 = 0.f, s10 = 0.f, c11 = 0.f, s11 = 0.f;
            int ia = 0, ib = 0;
            #pragma unroll 4
            for (int f = 1; f < 32; f++) {
                ia = (ia + u) & 63;
                ib = (ib + u + 16) & 63;
                float2 X0 = so[f * CO + o0];
                float2 X1 = so[f * CO + o0 + 16];
                float2 w0 = tw[ia];
                float2 w1 = tw[ib];
                c00 += X0.x * w0.x; s00 += X0.y * w0.y;
                c01 += X1.x * w0.x; s01 += X1.y * w0.y;
                c10 += X0.x * w1.x; s10 += X0.y * w1.y;
                c11 += X1.x * w1.x; s11 += X1.y * w1.y;
            }
            float x0a = so[o0].x,      xNa = so[32 * CO + o0].x;
            float x0b = so[o0 + 16].x, xNb = so[32 * CO + o0 + 16].x;
            float sg = (u & 1) ? -1.f : 1.f;
            float bA = x0a + sg * xNa, bB = x0b + sg * xNb;
            int jp0 = u, jp1 = u + 16;
            sfr[jp0 * 33 + o0]      = (bA + 2.f * (c00 - s00)) * inv;
            sfr[jp0 * 33 + o0 + 16] = (bB + 2.f * (c01 - s01)) * inv;
            if (jp0 >= 1) {
                sfr[(64 - jp0) * 33 + o0]      = (bA + 2.f * (c00 + s00)) * inv;
                sfr[(64 - jp0) * 33 + o0 + 16] = (bB + 2.f * (c01 + s01)) * inv;
            }
            sfr[jp1 * 33 + o0]      = (bA + 2.f * (c10 - s10)) * inv;
            sfr[jp1 * 33 + o0 + 16] = (bB + 2.f * (c11 - s11)) * inv;
            sfr[(64 - jp1) * 33 + o0]      = (bA + 2.f * (c10 + s10)) * inv;
            sfr[(64 - jp1) * 33 + o0 + 16] = (bB + 2.f * (c11 + s11)) * inv;
        }
        if (tid < 32) {          // jp = 32
            int o = tid;
            float acc = 0.f;
            #pragma unroll 4
            for (int f = 1; f < 32; f++) {
                float v = so[f * CO + o].x;
                acc += (f & 1) ? -v : v;
            }
            float bs = so[o].x + so[32 * CO + o].x;
            sfr[32 * 33 + o] = (bs + 2.f * acc) * inv;
        }
        __syncthreads();
        for (int i = tid; i < N0 * CO; i += 256) {
            int o = i >> 6, j = i & 63;
            float v = sfr[j * 33 + o];
            int s = (t == 0) ? ((j >= 32) ? (j - 32) : (8160 + j)) : (t * 64 + j - 32);
            y[(b * 64 + o) * LEN + s] = fmaxf(v + pbias[o], 0.f);
        }
    }
}

// ================= head1 einsum, f-major, 2bt x 2o tile, float4 x-loads =================
__global__ void k_head1e(const float* __restrict__ fk1_r, const float* __restrict__ fk1_i) {
    __shared__ float2 sfk[CI * CO];     // fk1[f]
    __shared__ float2 sxb[32 * CI];     // staging: 32 bt x 16 c (BN applied)
    int tid   = threadIdx.x;
    int chunk = blockIdx.x & 3;
    int f     = blockIdx.x >> 2;

    for (int i = tid; i < CI * CO; i += 256)
        sfk[i] = make_float2(fk1_r[f * CI * CO + i], fk1_i[f * CI * CO + i]);

    int wid = tid >> 5, lane = tid & 31;
    int o0 = lane & 15;
    int bl = lane >> 4;
    int btl = wid * 4 + bl * 2;          // local bt pair (btl, btl+1)
    for (int iter = 0; iter < 16; iter++) {
        int bt0 = chunk * 512 + iter * 32;
        __syncthreads();
        #pragma unroll
        for (int r = 0; r < 2; r++) {
            int idx = tid + r * 256;
            int bti = idx >> 4, c = idx & 15;
            int bt  = bt0 + bti;
            float4 st = g_stats[BB + (bt >> 5)];
            float2 z  = g_p1[(bt * F1 + f) * CI + c];
            sxb[idx] = make_float2(z.x * st.x + st.y, z.y * st.x + st.z);
        }
        __syncthreads();
        float r00 = 0.f, i00 = 0.f, r01 = 0.f, i01 = 0.f;
        float r10 = 0.f, i10 = 0.f, r11 = 0.f, i11 = 0.f;
        const float4* x0p = (const float4*)(sxb + btl * CI);
        const float4* x1p = (const float4*)(sxb + (btl + 1) * CI);
        #pragma unroll
        for (int c2 = 0; c2 < 8; c2++) {
            float4 X0 = x0p[c2];
            float4 X1 = x1p[c2];
            float2 k00 = sfk[(2 * c2) * CO + o0];
            float2 k01 = sfk[(2 * c2) * CO + o0 + 16];
            float2 k10 = sfk[(2 * c2 + 1) * CO + o0];
            float2 k11 = sfk[(2 * c2 + 1) * CO + o0 + 16];
            r00 += X0.x * k00.x - X0.y * k00.y;  i00 += X0.x * k00.y + X0.y * k00.x;
            r00 += X0.z * k10.x - X0.w * k10.y;  i00 += X0.z * k10.y + X0.w * k10.x;
            r01 += X0.x * k01.x - X0.y * k01.y;  i01 += X0.x * k01.y + X0.y * k01.x;
            r01 += X0.z * k11.x - X0.w * k11.y;  i01 += X0.z * k11.y + X0.w * k11.x;
            r10 += X1.x * k00.x - X1.y * k00.y;  i10 += X1.x * k00.y + X1.y * k00.x;
            r10 += X1.z * k10.x - X1.w * k10.y;  i10 += X1.z * k10.y + X1.w * k10.x;
            r11 += X1.x * k01.x - X1.y * k01.y;  i11 += X1.x * k01.y + X1.y * k01.x;
            r11 += X1.z * k11.x - X1.w * k11.y;  i11 += X1.z * k11.y + X1.w * k11.x;
        }
        long gb = (long)(bt0 + btl) * F1 + f;
        g_out1[gb * CO + o0]             = make_float2(r00, i00);
        g_out1[gb * CO + o0 + 16]        = make_float2(r01, i01);
        g_out1[(gb + F1) * CO + o0]      = make_float2(r10, i10);
        g_out1[(gb + F1) * CO + o0 + 16] = make_float2(r11, i11);
    }
}

// ===== iSTFT-256 : parity split + 4j x 4-consecutive-o tiling (float4 X loads) + bias/relu =====
__global__ void k_istft1(const float* __restrict__ pbias, float* __restrict__ y) {
    extern __shared__ char smraw[];
    float2* sX  = (float2*)smraw;            // F1*CO
    float2* tw  = sX + F1 * CO;              // 256
    float*  sfr = (float*)(tw + 256);        // 256*33 padded

    int tid = threadIdx.x;
    int b = blockIdx.x >> 5, t = blockIdx.x & 31;
    int fb = (b * T1 + t) * (F1 * CO);
    for (int i = tid; i < F1 * CO; i += 128) sX[i] = g_out1[fb + i];
    for (int i = tid; i < 256; i += 128) {
        float s, c; sincospif(i * (1.0f / 128.0f), &s, &c);
        tw[i] = make_float2(c, s);
    }
    __syncthreads();
    const float inv = 1.0f / 256.0f;
    int u  = tid >> 3;        // jp = u + 16k, k=0..3 (jp in 0..63)
    int og = tid & 7;         // o = 4*og + m, m=0..3 (consecutive)
    float Ce[4][4], Co[4][4], Se[4][4], So[4][4];
    int io[4], ie[4], jq[4];
    #pragma unroll
    for (int k = 0; k < 4; k++) {
        jq[k] = u + 16 * k;
        io[k] = jq[k];
        ie[k] = 0;
        #pragma unroll
        for (int m = 0; m < 4; m++) { Ce[k][m] = Co[k][m] = Se[k][m] = So[k][m] = 0.f; }
    }
    // h = 0 : f = 1 (odd only)
    {
        const float4* p = (const float4*)(sX + CO + 4 * og);
        float4 Xa = p[0], Xb = p[1];
        #pragma unroll
        for (int k = 0; k < 4; k++) {
            float2 w = tw[io[k]];
            Co[k][0] += Xa.x * w.x;  So[k][0] += Xa.y * w.y;
            Co[k][1] += Xa.z * w.x;  So[k][1] += Xa.w * w.y;
            Co[k][2] += Xb.x * w.x;  So[k][2] += Xb.y * w.y;
            Co[k][3] += Xb.z * w.x;  So[k][3] += Xb.w * w.y;
        }
    }
    #pragma unroll 2
    for (int h = 1; h < 64; h++) {
        const float4* pe = (const float4*)(sX + (2 * h) * CO + 4 * og);
        const float4* po = (const float4*)(sX + (2 * h + 1) * CO + 4 * og);
        float4 Ea = pe[0], Eb = pe[1];
        float4 Oa = po[0], Ob = po[1];
        #pragma unroll
        for (int k = 0; k < 4; k++) {
            ie[k] = (ie[k] + 2 * jq[k]) & 255;
            io[k] = (io[k] + 2 * jq[k]) & 255;
            float2 we = tw[ie[k]];
            float2 wo = tw[io[k]];
            Ce[k][0] += Ea.x * we.x;  Se[k][0] += Ea.y * we.y;
            Ce[k][1] += Ea.z * we.x;  Se[k][1] += Ea.w * we.y;
            Ce[k][2] += Eb.x * we.x;  Se[k][2] += Eb.y * we.y;
            Ce[k][3] += Eb.z * we.x;  Se[k][3] += Eb.w * we.y;
            Co[k][0] += Oa.x * wo.x;  So[k][0] += Oa.y * wo.y;
            Co[k][1] += Oa.z * wo.x;  So[k][1] += Oa.w * wo.y;
            Co[k][2] += Ob.x * wo.x;  So[k][2] += Ob.y * wo.y;
            Co[k][3] += Ob.z * wo.x;  So[k][3] += Ob.w * wo.y;
        }
    }
    float sg = (u & 1) ? -1.f : 1.f;
    #pragma unroll
    for (int m = 0; m < 4; m++) {
        int o = 4 * og + m;
        float x0 = sX[o].x, xN = sX[128 * CO + o].x;
        float bs = x0 + sg * xN;
        #pragma unroll
        for (int k = 0; k < 4; k++) {
            int j = jq[k];
            float A = Ce[k][m], B = Co[k][m], D = Se[k][m], E = So[k][m];
            float cp = A + B, cm = A - B, sp = D + E, sm = D - E;
            sfr[j * 33 + o] = (bs + 2.f * (cp - sp)) * inv;
            if (j) sfr[(256 - j) * 33 + o] = (bs + 2.f * (cp + sp)) * inv;
            sfr[(128 - j) * 33 + o] = (bs + 2.f * (cm + sm)) * inv;
            if (j) sfr[(128 + j) * 33 + o] = (bs + 2.f * (cm - sm)) * inv;
        }
    }
    // jp = 64 special: rows 64 and 192
    if (tid < 32) {
        int o = tid;
        float Sr = 0.f, Si = 0.f;
        #pragma unroll 4
        for (int g = 1; g < 64; g++) {
            float v = sX[(2 * g) * CO + o].x;
            Sr += (g & 1) ? -v : v;
        }
        #pragma unroll 4
        for (int g = 0; g < 64; g++) {
            float v = sX[(2 * g + 1) * CO + o].y;
            Si += (g & 1) ? -v : v;
        }
        float bs = sX[o].x + sX[128 * CO + o].x;
        sfr[64 * 33 + o]  = (bs + 2.f * (Sr - Si)) * inv;
        sfr[192 * 33 + o] = (bs + 2.f * (Sr + Si)) * inv;
    }
    __syncthreads();
    for (int i = tid; i < N1 * CO; i += 128) {
        int o = i >> 8, j = i & 255;
        float v = sfr[j * 33 + o];
        int s = (t == 0) ? ((j >= 128) ? (j - 128) : (8064 + j)) : (t * 256 + j - 128);
        y[(b * 64 + 32 + o) * LEN + s] = fmaxf(v + pbias[32 + o], 0.f);
    }
}

// ================= launcher =================
extern "C" void kernel_launch(void* const* d_in, const int* in_sizes, int n_in,
                              void* d_out, int out_size) {
    const float* x        = (const float*)d_in[0];
    const float* bn_gamma = (const float*)d_in[1];
    const float* bn_beta  = (const float*)d_in[2];
    const float* mk_r     = (const float*)d_in[3];
    const float* mk_i     = (const float*)d_in[4];
    const float* mb_r     = (const float*)d_in[5];
    const float* mb_i     = (const float*)d_in[6];
    const float* fk0_r    = (const float*)d_in[7];
    const float* fk0_i    = (const float*)d_in[8];
    const float* fk1_r    = (const float*)d_in[9];
    const float* fk1_i    = (const float*)d_in[10];
    const float* pbias    = (const float*)d_in[11];
    float* y = (float*)d_out;

    const int SMEM0 = (F0 * CI * CO + F0 * CI + F0 * CO + 64) * 8 + 64 * 33 * 4;   // head0
    const int SMEM2 = (F1 * CO + 256) * 8 + 256 * 33 * 4;                           // istft1

    cudaFuncSetAttribute(k_head0,  cudaFuncAttributeMaxDynamicSharedMemorySize, SMEM0);
    cudaFuncSetAttribute(k_istft1, cudaFuncAttributeMaxDynamicSharedMemorySize, SMEM2);

    k_zero  <<<1, 384>>>();
    k_stft0 <<<BB * T0, 128>>>(x);
    k_stft1 <<<BB * T1, 128>>>(x);
    k_merge <<<dim3((T1 * F0 * CI + 255) / 256, BB), 256>>>(mk_r, mk_i, mb_r, mb_i);
    k_stats_fin <<<1, 128>>>(bn_gamma, bn_beta);
    k_head0 <<<BB * 8, 256, SMEM0>>>(fk0_r, fk0_i, pbias, y);
    k_head1e<<<F1 * 4, 256>>>(fk1_r, fk1_i);
    k_istft1<<<BB * T1, 128, SMEM2>>>(pbias, y);
}